// round 14
// baseline (speedup 1.0000x reference)
#include <cuda_runtime.h>
#include <math.h>

// FNetBlock: B=4, L=512, D=64, LAG=32  (2048 rows)
// out[row,d] = b0 + c[row,d] * (c>0 ? A_pos[row] : A_neg[row])
//   c[row,d] = sum_e x[row,e] cos(2*pi*d*e/64)
//   m[row,f] = sum_j mask[row,j] cos(2*pi*f*j/512), f=0..256
//   s = sort(m);  A_pos = sum_k W[k] s[k]      + W[32+k] s[225+k]
//                 A_neg = sum_k W[k] s[256-k]  + W[32+k] s[31-k]
// 1 row per 128-thread block (2048 blocks -> ~2x warp supply vs 2-row).
// Packed f32x2 4-phase Chebyshev DFT (zero negations, signs baked into
// fold), cospif+sqrt trig, single-pair register bitonic sort per thread,
// R7 merge/epilogue skeleton with packed x-transform on warps 2-3.

typedef unsigned long long u64t;
__device__ __forceinline__ u64t pk2(float lo, float hi) {
    u64t r; asm("mov.b64 %0,{%1,%2};" : "=l"(r) : "f"(lo), "f"(hi)); return r;
}
__device__ __forceinline__ void upk2(float& lo, float& hi, u64t v) {
    asm("mov.b64 {%0,%1},%2;" : "=f"(lo), "=f"(hi) : "l"(v));
}
__device__ __forceinline__ u64t fma2_(u64t a, u64t b, u64t c) {
    u64t d; asm("fma.rn.f32x2 %0,%1,%2,%3;" : "=l"(d) : "l"(a), "l"(b), "l"(c)); return d;
}

__global__ __launch_bounds__(128) void fnet_kernel(
    const float* __restrict__ x,     // [2048, 64]
    const float* __restrict__ mask,  // [2048, 512]
    const float* __restrict__ W,     // [64]
    const float* __restrict__ bvec,  // [1]
    float* __restrict__ out)         // [2048, 64]
{
    __shared__ __align__(16) float  sb[512];            // mask row (u)
    __shared__ __align__(16) float2 foldP[2][68];       // [parity][a]=(we,wo), signed
    __shared__ __align__(16) float  xs[64];             // x row, signed per float4
    __shared__ float  slow[4][32];
    __shared__ float  shigh[4][32];
    __shared__ float  mbuf[4][32];
    __shared__ float  sm128;
    __shared__ float  sPP[2], sPN[2];

    const int tid  = threadIdx.x;     // 0..127
    const int lane = tid & 31;
    const int wr   = tid >> 5;        // warp 0..3
    const int row  = blockIdx.x;

    // ---- trig early: one cospif; sines/half-angle via exact sqrt identities ----
    const int f = tid;
    const float cphi = cospif((float)f * (1.0f/128.0f));          // cos(phi), phi=2*pi*f/256
    const float sphi = sqrtf(fmaxf(0.0f, 1.0f - cphi * cphi));    // sin(phi) >= 0 on [0,pi)
    const float cpsi = sqrtf(0.5f * (1.0f + cphi));               // cos(psi), psi=phi/2
    const float spsi = sqrtf(fmaxf(0.0f, 0.5f * (1.0f - cphi)));  // sin(psi) >= 0

    // ---- coalesced vectorized loads ----
    {
        const float4* m4 = (const float4*)(mask + row * 512);
        ((float4*)sb)[tid] = m4[tid];
    }
    if (tid < 16) {
        const float4* x4 = (const float4*)(x + row * 64);
        float4 v = x4[tid];
        if (tid & 1) { v.x = -v.x; v.y = -v.y; v.z = -v.z; v.w = -v.w; } // bake (+,+,-,-)
        ((float4*)xs)[tid] = v;
    }
    __syncthreads();

    // ---- double fold with chain-phase sign baked in ----
    {
        const int pp = tid >> 6;
        const int a  = tid & 63;
        const float s  = pp ? -1.0f : 1.0f;
        const float sg = (a & 4) ? -1.0f : 1.0f;   // sign for chain step g=a>>1
        const float* u = sb;
        float we, wo;
        if (a == 0) {
            we = fmaf(s, u[256], u[0]);
            wo = (u[1] + u[511]) + s * (u[255] + u[257]);
        } else {
            we = (u[2*a] + u[512-2*a]) + s * (u[256-2*a] + u[256+2*a]);
            wo = (u[2*a+1] + u[511-2*a]) + s * (u[255-2*a] + u[257+2*a]);
        }
        foldP[pp][a] = make_float2(we * sg, wo * sg);
    }
    __syncthreads();

    // ---- folded DFT: 4-phase packed chains, zero negations ----
    const int p = f & 1;
    const float c2 = fmaf(2.0f*cphi, cphi, -1.0f);      // cos(2phi)
    const float s2 = 2.0f * sphi * cphi;                // sin(2phi)
    const float wpe0 = fmaf(cpsi, c2,  spsi * s2);      // cos(psi-2phi)
    const float wo0  = fmaf(cpsi, cphi, -(spsi * sphi));// cos(psi+phi)
    const float wpo0 = fmaf(cpsi, cphi,  (spsi * sphi));// cos(psi-phi)

    const u64t T2  = pk2( 2.0f * c2,  2.0f * c2);
    const u64t NT2 = pk2(-2.0f * c2, -2.0f * c2);
    u64t M0 = pk2(1.0f,  cpsi);   u64t P0 = pk2(-c2,  -wpe0);
    u64t M1 = pk2(cphi,  wo0);    u64t P1 = pk2(-cphi, -wpo0);

    u64t A0 = 0, A1 = 0;
    const ulonglong2* wq = (const ulonglong2*)&foldP[p][0];
    #pragma unroll
    for (int j = 0; j < 8; ++j) {
        ulonglong2 qa;
        qa = wq[4*j];                           // g = 4j   (+)
        A0 = fma2_(qa.x, M0, A0);  A1 = fma2_(qa.y, M1, A1);
        u64t n0 = fma2_(T2, M0, P0), n1 = fma2_(T2, M1, P1);
        qa = wq[4*j + 1];                       // g = 4j+1 (+)
        A0 = fma2_(qa.x, n0, A0);  A1 = fma2_(qa.y, n1, A1);
        u64t m0 = fma2_(NT2, n0, M0), m1 = fma2_(NT2, n1, M1);
        qa = wq[4*j + 2];                       // g = 4j+2 (-)
        A0 = fma2_(qa.x, m0, A0);  A1 = fma2_(qa.y, m1, A1);
        u64t r0 = fma2_(T2, m0, n0), r1 = fma2_(T2, m1, n1);
        qa = wq[4*j + 3];                       // g = 4j+3 (-)
        A0 = fma2_(qa.x, r0, A0);  A1 = fma2_(qa.y, r1, A1);
        M0 = fma2_(NT2, r0, m0);  M1 = fma2_(NT2, r1, m1);
        P0 = r0;  P1 = r1;
    }
    float v0, v1;
    {
        float E, O, e1, o1;
        upk2(E, O, A0); upk2(e1, o1, A1); E += e1; O += o1;
        if (p == 0) {                  // tail: v_e[64]*cos(pi*f/2)
            float sgn = (f & 2) ? -1.f : 1.f;
            E = fmaf(sgn, sb[128] + sb[384], E);
        }
        v0 = E + O;    // m[f]
        v1 = E - O;    // m[256-f]
    }

    // ---- m[128] by warp 3 (float4 loads) ----
    if (wr == 3) {
        const float4* u4 = (const float4*)sb;
        float s = 0.f;
        #pragma unroll
        for (int q = 0; q < 4; q++) {
            float4 v = u4[lane + q * 32];
            s += v.x - v.z;
        }
        #pragma unroll
        for (int o = 16; o; o >>= 1) s += __shfl_xor_sync(0xffffffffu, s, o);
        if (lane == 0) sm128 = s;
    }

    // ---- warp bitonic sort of 64 (2 regs/lane), ascending ----
    #pragma unroll
    for (int k = 2; k <= 32; k <<= 1) {
        #pragma unroll
        for (int j = k >> 1; j > 0; j >>= 1) {
            bool up0 = ((lane & k) == 0);
            bool up1 = (((lane + 32) & k) == 0);
            float p0 = __shfl_xor_sync(0xffffffffu, v0, j);
            float p1 = __shfl_xor_sync(0xffffffffu, v1, j);
            bool low = ((lane & j) == 0);
            v0 = (low == up0) ? fminf(v0, p0) : fmaxf(v0, p0);
            v1 = (low == up1) ? fminf(v1, p1) : fmaxf(v1, p1);
        }
    }
    {   // k = 64 stage: j=32 crosses regs, then clean
        float lo = fminf(v0, v1), hi = fmaxf(v0, v1);
        v0 = lo; v1 = hi;
        #pragma unroll
        for (int j = 16; j > 0; j >>= 1) {
            float p0 = __shfl_xor_sync(0xffffffffu, v0, j);
            float p1 = __shfl_xor_sync(0xffffffffu, v1, j);
            bool low = ((lane & j) == 0);
            v0 = low ? fminf(v0, p0) : fmaxf(v0, p0);
            v1 = low ? fminf(v1, p1) : fmaxf(v1, p1);
        }
    }
    slow [wr][lane] = v0;   // bottom 32 ascending
    shigh[wr][lane] = v1;   // top 32 ascending
    __syncthreads();

    // ---- level-1 merges (keep 32 extremes of 64) ----
    {
        float res;
        if      (wr == 0) res = fminf(slow [0][lane], slow [1][31-lane]);
        else if (wr == 1) res = fminf(slow [2][lane], slow [3][31-lane]);
        else if (wr == 2) res = fmaxf(shigh[0][lane], shigh[1][31-lane]);
        else              res = fmaxf(shigh[2][lane], shigh[3][31-lane]);
        #pragma unroll
        for (int j = 16; j > 0; j >>= 1) {   // bitonic clean -> ascending
            float pv = __shfl_xor_sync(0xffffffffu, res, j);
            res = ((lane & j) == 0) ? fminf(res, pv) : fmaxf(res, pv);
        }
        mbuf[wr][lane] = res;
    }
    __syncthreads();

    // ---- final merges + m128 insert + epilogue dot  |  x-transform ----
    float cval = 0.f;
    if (wr == 0) {
        float lowv = fminf(mbuf[0][lane], mbuf[1][31-lane]);
        #pragma unroll
        for (int j = 16; j > 0; j >>= 1) {
            float pv = __shfl_xor_sync(0xffffffffu, lowv, j);
            lowv = ((lane & j) == 0) ? fminf(lowv, pv) : fmaxf(lowv, pv);
        }
        float m128 = sm128;
        unsigned bal = __ballot_sync(0xffffffffu, lowv < m128);
        int cnt = __popc(bal);
        float sh = __shfl_up_sync(0xffffffffu, lowv, 1);
        if (lane >= cnt) lowv = (lane == cnt) ? m128 : sh;
        float pp = __ldg(&W[lane])      * lowv;
        float pn = __ldg(&W[63 - lane]) * lowv;
        #pragma unroll
        for (int o = 16; o; o >>= 1) {
            pp += __shfl_xor_sync(0xffffffffu, pp, o);
            pn += __shfl_xor_sync(0xffffffffu, pn, o);
        }
        if (lane == 0) { sPP[0] = pp; sPN[0] = pn; }
    } else if (wr == 1) {
        float highv = fmaxf(mbuf[2][lane], mbuf[3][31-lane]);
        #pragma unroll
        for (int j = 16; j > 0; j >>= 1) {
            float pv = __shfl_xor_sync(0xffffffffu, highv, j);
            highv = ((lane & j) == 0) ? fminf(highv, pv) : fmaxf(highv, pv);
        }
        float m128 = sm128;
        unsigned bal = __ballot_sync(0xffffffffu, highv < m128);
        int cnt = __popc(bal);
        float shd = __shfl_down_sync(0xffffffffu, highv, 1);
        highv = (lane + 1 < cnt) ? shd : ((lane + 1 == cnt) ? m128 : highv);
        float pp = __ldg(&W[32 + lane]) * highv;
        float pn = __ldg(&W[31 - lane]) * highv;
        #pragma unroll
        for (int o = 16; o; o >>= 1) {
            pp += __shfl_xor_sync(0xffffffffu, pp, o);
            pn += __shfl_xor_sync(0xffffffffu, pn, o);
        }
        if (lane == 0) { sPP[1] = pp; sPN[1] = pn; }
    } else {
        // x-transform (d = tid-64), packed 4-phase chains
        int d = tid - 64;
        float cth = cospif((float)d * (1.0f/32.0f));     // cos(theta), theta = 2*pi*d/64
        float c2t = fmaf(2.0f*cth, cth, -1.0f);          // cos(2theta)
        const u64t Tx  = pk2( 2.0f*c2t,  2.0f*c2t);
        const u64t NTx = pk2(-2.0f*c2t, -2.0f*c2t);
        u64t M  = pk2(1.0f, cth);                        // (cos(2h t), cos((2h+1)t))
        u64t P  = pk2(-c2t, -cth);
        u64t acc = 0;
        const u64t* xrp = (const u64t*)xs;               // signed (x[2h], x[2h+1])
        #pragma unroll
        for (int j = 0; j < 8; ++j) {
            acc = fma2_(xrp[4*j],     M, acc);
            u64t n = fma2_(Tx, M, P);
            acc = fma2_(xrp[4*j + 1], n, acc);
            u64t m = fma2_(NTx, n, M);
            acc = fma2_(xrp[4*j + 2], m, acc);
            u64t r = fma2_(Tx, m, n);
            acc = fma2_(xrp[4*j + 3], r, acc);
            M = fma2_(NTx, r, m);  P = r;
        }
        float ca, cb;
        upk2(ca, cb, acc);
        cval = ca + cb;
    }
    __syncthreads();

    // ---- output (warps 2,3; coalesced) ----
    if (wr >= 2) {
        int d = tid - 64;
        float Ap = sPP[0] + sPP[1];
        float An = sPN[0] + sPN[1];
        float A = (cval > 0.f) ? Ap : An;
        out[row * 64 + d] = fmaf(cval, A, bvec[0]);
    }
}

extern "C" void kernel_launch(void* const* d_in, const int* in_sizes, int n_in,
                              void* d_out, int out_size) {
    const float* x    = (const float*)d_in[0];
    const float* mask = (const float*)d_in[1];
    const float* W    = (const float*)d_in[2];
    const float* b    = (const float*)d_in[3];
    fnet_kernel<<<2048, 128>>>(x, mask, W, b, (float*)d_out);
}